// round 1
// baseline (speedup 1.0000x reference)
#include <cuda_runtime.h>
#include <stdint.h>

// Quantum 2x2 gate apply on qubit axis TARGET=5 of state (2,)^24 x (4,) f32.
// Row-major: target-axis stride = 2^18 * 4 = 2^20 elements = 2^18 float4 units.
// out[t=0] = p00*s0 + p01*s1 ; out[t=1] = p10*s0 + p11*s1.
//
// Total float4 units: 2^24 * 4 / 4 = 2^24. Pairs: 2^23.
// For pair-index v in [0, 2^23):
//   low  = v & (2^18 - 1)            (contiguous within lower block)
//   high = v >> 18
//   idx0 = (high << 19) | low        (target bit = 0)
//   idx1 = idx0 + 2^18               (target bit = 1)

static constexpr int TARGET_SHIFT_F4 = 18;            // log2(stride in float4 units)
static constexpr long long NPAIRS = 1LL << 23;        // 8,388,608 pairs of float4

__global__ __launch_bounds__(256)
void gate_apply_kernel(const float4* __restrict__ state,
                       const float*  __restrict__ pauli,
                       float4* __restrict__ out)
{
    long long v = (long long)blockIdx.x * blockDim.x + threadIdx.x;
    if (v >= NPAIRS) return;

    const float p00 = pauli[0];
    const float p01 = pauli[1];
    const float p10 = pauli[2];
    const float p11 = pauli[3];

    long long low  = v & ((1LL << TARGET_SHIFT_F4) - 1);
    long long high = v >> TARGET_SHIFT_F4;
    long long idx0 = (high << (TARGET_SHIFT_F4 + 1)) | low;
    long long idx1 = idx0 + (1LL << TARGET_SHIFT_F4);

    float4 s0 = state[idx0];
    float4 s1 = state[idx1];

    float4 o0, o1;
    o0.x = p00 * s0.x + p01 * s1.x;
    o0.y = p00 * s0.y + p01 * s1.y;
    o0.z = p00 * s0.z + p01 * s1.z;
    o0.w = p00 * s0.w + p01 * s1.w;

    o1.x = p10 * s0.x + p11 * s1.x;
    o1.y = p10 * s0.y + p11 * s1.y;
    o1.z = p10 * s0.z + p11 * s1.z;
    o1.w = p10 * s0.w + p11 * s1.w;

    out[idx0] = o0;
    out[idx1] = o1;
}

extern "C" void kernel_launch(void* const* d_in, const int* in_sizes, int n_in,
                              void* d_out, int out_size)
{
    const float4* state = (const float4*)d_in[0];
    const float*  pauli = (const float*)d_in[1];
    float4* out = (float4*)d_out;

    const int threads = 256;
    const long long blocks = (NPAIRS + threads - 1) / threads;  // 32768
    gate_apply_kernel<<<(unsigned)blocks, threads>>>(state, pauli, out);
}

// round 2
// speedup vs baseline: 1.0004x; 1.0004x over previous
#include <cuda_runtime.h>
#include <stdint.h>

// Quantum 2x2 gate apply on qubit axis TARGET=5 of state (2,)^24 x (4,) f32.
// Row-major: target-axis stride = 2^18 float4 units.
// Each thread handles TWO pairs (v and v + NPAIRS/2) -> 4 independent
// front-batched float4 loads (MLP_p1=4), 4 stores. Coalescing preserved:
// consecutive threads touch consecutive float4 within each stream.

static constexpr int SHIFT = 18;                      // target stride, float4 units
static constexpr long long NPAIRS = 1LL << 23;        // pairs of float4
static constexpr long long HALF   = NPAIRS >> 1;      // 2^22

__device__ __forceinline__ float4 ldcs4(const float4* p) {
    float4 v;
    asm volatile("ld.global.cs.v4.f32 {%0,%1,%2,%3}, [%4];"
                 : "=f"(v.x), "=f"(v.y), "=f"(v.z), "=f"(v.w) : "l"(p));
    return v;
}

__device__ __forceinline__ void stcs4(float4* p, float4 v) {
    asm volatile("st.global.cs.v4.f32 [%0], {%1,%2,%3,%4};"
                 :: "l"(p), "f"(v.x), "f"(v.y), "f"(v.z), "f"(v.w));
}

__global__ __launch_bounds__(256)
void gate_apply_kernel(const float4* __restrict__ state,
                       const float*  __restrict__ pauli,
                       float4* __restrict__ out)
{
    long long v = (long long)blockIdx.x * blockDim.x + threadIdx.x;   // [0, HALF)

    const float p00 = pauli[0];
    const float p01 = pauli[1];
    const float p10 = pauli[2];
    const float p11 = pauli[3];

    // pair A: v ;  pair B: v + HALF
    long long lowA  = v & ((1LL << SHIFT) - 1);
    long long idxA0 = ((v >> SHIFT) << (SHIFT + 1)) | lowA;
    long long idxA1 = idxA0 + (1LL << SHIFT);

    long long w = v + HALF;
    long long lowB  = w & ((1LL << SHIFT) - 1);
    long long idxB0 = ((w >> SHIFT) << (SHIFT + 1)) | lowB;
    long long idxB1 = idxB0 + (1LL << SHIFT);

    // front-batch all 4 loads
    float4 a0 = ldcs4(state + idxA0);
    float4 a1 = ldcs4(state + idxA1);
    float4 b0 = ldcs4(state + idxB0);
    float4 b1 = ldcs4(state + idxB1);

    float4 oA0, oA1, oB0, oB1;
    oA0.x = p00*a0.x + p01*a1.x;  oA0.y = p00*a0.y + p01*a1.y;
    oA0.z = p00*a0.z + p01*a1.z;  oA0.w = p00*a0.w + p01*a1.w;
    oA1.x = p10*a0.x + p11*a1.x;  oA1.y = p10*a0.y + p11*a1.y;
    oA1.z = p10*a0.z + p11*a1.z;  oA1.w = p10*a0.w + p11*a1.w;

    oB0.x = p00*b0.x + p01*b1.x;  oB0.y = p00*b0.y + p01*b1.y;
    oB0.z = p00*b0.z + p01*b1.z;  oB0.w = p00*b0.w + p01*b1.w;
    oB1.x = p10*b0.x + p11*b1.x;  oB1.y = p10*b0.y + p11*b1.y;
    oB1.z = p10*b0.z + p11*b1.z;  oB1.w = p10*b0.w + p11*b1.w;

    stcs4(out + idxA0, oA0);
    stcs4(out + idxA1, oA1);
    stcs4(out + idxB0, oB0);
    stcs4(out + idxB1, oB1);
}

extern "C" void kernel_launch(void* const* d_in, const int* in_sizes, int n_in,
                              void* d_out, int out_size)
{
    const float4* state = (const float4*)d_in[0];
    const float*  pauli = (const float*)d_in[1];
    float4* out = (float4*)d_out;

    const int threads = 256;
    const long long blocks = (HALF + threads - 1) / threads;  // 16384
    gate_apply_kernel<<<(unsigned)blocks, threads>>>(state, pauli, out);
}